// round 10
// baseline (speedup 1.0000x reference)
#include <cuda_runtime.h>
#include <cuda_fp16.h>

// AOLayer: out[b,n,a] = ang * rad, B=512,N=32,A=256,P=6.
// Round 10: r4's MUFU halving (f16x2 exp2 pairs two rows per MUFU op) rebuilt
// with __half2 intrinsics (no asm-barrier MOV churn) on the r5 skeleton
// (grid 1024, ROWS=16, full unroll). Packed float2 SMEM -> LDS.64.
// f32 args + f32 accumulation; f16 only inside cvt->ex2->cvt (rel_err ~7e-4).

#define A_DIM 256
#define P_DIM 6
#define BN_DIM (512 * 32)
#define ROWS_PER_BLOCK 16
#define NPAIRS (ROWS_PER_BLOCK / 2)

__global__ void __launch_bounds__(A_DIM) aolayer_kernel(
    const float* __restrict__ pos,      // [BN, 3]
    const float* __restrict__ centers,  // [A, 3]
    const float* __restrict__ exps,     // [A, P]
    const float* __restrict__ coeffs,   // [A, P]
    const int*   __restrict__ powers,   // [A, 3]
    float* __restrict__ out)            // [BN, A]
{
    const int a = threadIdx.x;

    // ---- per-atom constants (once per block) ----
    const float ncx = -centers[a * 3 + 0];
    const float ncy = -centers[a * 3 + 1];
    const float ncz = -centers[a * 3 + 2];

    const float NEG_LOG2E = -1.4426950408889634f;
    float ep[P_DIM], co[P_DIM];
#pragma unroll
    for (int p = 0; p < P_DIM; p++) {
        ep[p] = exps[a * P_DIM + p] * NEG_LOG2E;
        co[p] = coeffs[a * P_DIM + p];
    }

    const int px = powers[a * 3 + 0];
    const int py = powers[a * 3 + 1];
    const int pz = powers[a * 3 + 2];
    // loop-invariant predicates -> ISETPs hoisted out of the unrolled loop
    const bool lx = (px >= 1), qx = (px == 2);
    const bool ly = (py >= 1), qy = (py == 2);
    const bool lz = (pz >= 1), qz = (pz == 2);

    // ---- stage pos pairs: spos2[pr*3+d] = {row 2pr dim d, row 2pr+1 dim d} ----
    __shared__ float2 spos2[NPAIRS * 3];
    const int row0 = blockIdx.x * ROWS_PER_BLOCK;
    if (threadIdx.x < NPAIRS * 3) {
        const int pr = threadIdx.x / 3;
        const int d  = threadIdx.x % 3;
        spos2[threadIdx.x] = make_float2(pos[(row0 + 2 * pr) * 3 + d],
                                         pos[(row0 + 2 * pr + 1) * 3 + d]);
    }
    __syncthreads();

    float* out_base = out + (size_t)row0 * A_DIM + a;

#pragma unroll
    for (int pr = 0; pr < NPAIRS; pr++) {
        const float2 xp = spos2[pr * 3 + 0];   // LDS.64
        const float2 yp = spos2[pr * 3 + 1];
        const float2 zp = spos2[pr * 3 + 2];

        const float dx0 = xp.x + ncx, dx1 = xp.y + ncx;
        const float dy0 = yp.x + ncy, dy1 = yp.y + ncy;
        const float dz0 = zp.x + ncz, dz1 = zp.y + ncz;

        const float r2_0 = fmaf(dx0, dx0, fmaf(dy0, dy0, dz0 * dz0));
        const float r2_1 = fmaf(dx1, dx1, fmaf(dy1, dy1, dz1 * dz1));

        // radial: one f16x2 exp2 per p serves both rows (6 MUFU per pair).
        // args computed in f32 (exact-ish), accumulation in f32.
        __half2 e0 = h2exp2(__floats2half2_rn(ep[0] * r2_0, ep[0] * r2_1));
        float rad0 = co[0] * __low2float(e0);
        float rad1 = co[0] * __high2float(e0);
#pragma unroll
        for (int p = 1; p < P_DIM; p++) {
            __half2 e = h2exp2(__floats2half2_rn(ep[p] * r2_0, ep[p] * r2_1));
            rad0 = fmaf(co[p], __low2float(e), rad0);
            rad1 = fmaf(co[p], __high2float(e), rad1);
        }

        // angular as predicated muls (predicates loop-invariant)
        float o0 = rad0, o1 = rad1;
        if (lx) { o0 *= dx0; o1 *= dx1; }
        if (qx) { o0 *= dx0; o1 *= dx1; }
        if (ly) { o0 *= dy0; o1 *= dy1; }
        if (qy) { o0 *= dy0; o1 *= dy1; }
        if (lz) { o0 *= dz0; o1 *= dz1; }
        if (qz) { o0 *= dz0; o1 *= dz1; }

        out_base[(2 * pr) * A_DIM] = o0;
        out_base[(2 * pr + 1) * A_DIM] = o1;
    }
}

extern "C" void kernel_launch(void* const* d_in, const int* in_sizes, int n_in,
                              void* d_out, int out_size) {
    const float* pos     = (const float*)d_in[0];
    const float* centers = (const float*)d_in[1];
    const float* exps    = (const float*)d_in[2];
    const float* coeffs  = (const float*)d_in[3];
    const int*   powers  = (const int*)d_in[4];
    float* out = (float*)d_out;

    dim3 grid(BN_DIM / ROWS_PER_BLOCK);  // 1024 blocks
    dim3 block(A_DIM);                   // 256 threads, one per atom
    aolayer_kernel<<<grid, block>>>(pos, centers, exps, coeffs, powers, out);
}

// round 11
// speedup vs baseline: 1.1544x; 1.1544x over previous
#include <cuda_runtime.h>
#include <cuda_fp16.h>

// AOLayer: out[b,n,a] = ang * rad, B=512,N=32,A=256,P=6.
// Round 11: fold coefficients into exponents: c*2^(e*r2) = sgn(c)*2^(e*r2+log2|c|).
// Per p per row-pair: 2 FFMA (f32 args) + 1 cvt + 1 h2exp2 (MUFU) + 1 HFMA2.
// Cuts issue slots, MUFU ops, and fma-pipe ops simultaneously (the three
// co-saturated resources per r1-r10 evidence). f16 accumulation in two
// independent half2 accumulators; predicted rel_err ~8e-4 (<1e-3).

#define A_DIM 256
#define P_DIM 6
#define BN_DIM (512 * 32)
#define ROWS_PER_BLOCK 16
#define NPAIRS (ROWS_PER_BLOCK / 2)

__global__ void __launch_bounds__(A_DIM) aolayer_kernel(
    const float* __restrict__ pos,      // [BN, 3]
    const float* __restrict__ centers,  // [A, 3]
    const float* __restrict__ exps,     // [A, P]
    const float* __restrict__ coeffs,   // [A, P]
    const int*   __restrict__ powers,   // [A, 3]
    float* __restrict__ out)            // [BN, A]
{
    const int a = threadIdx.x;

    // ---- per-atom constants (once per block) ----
    const float ncx = -centers[a * 3 + 0];
    const float ncy = -centers[a * 3 + 1];
    const float ncz = -centers[a * 3 + 2];

    const float NEG_LOG2E = -1.4426950408889634f;
    float ep[P_DIM], lc[P_DIM];
    __half2 sg[P_DIM];
#pragma unroll
    for (int p = 0; p < P_DIM; p++) {
        ep[p] = exps[a * P_DIM + p] * NEG_LOG2E;
        const float c = coeffs[a * P_DIM + p];
        lc[p] = __log2f(fabsf(c));               // -inf if c==0 -> exp2 -> 0 (ok)
        sg[p] = __float2half2_rn(copysignf(1.0f, c));
    }

    const int px = powers[a * 3 + 0];
    const int py = powers[a * 3 + 1];
    const int pz = powers[a * 3 + 2];
    // loop-invariant predicates -> ISETPs hoisted out of the unrolled loop
    const bool lx = (px >= 1), qx = (px == 2);
    const bool ly = (py >= 1), qy = (py == 2);
    const bool lz = (pz >= 1), qz = (pz == 2);

    // ---- stage pos pairs: spos2[pr*3+d] = {row 2pr, row 2pr+1} dim d ----
    __shared__ float2 spos2[NPAIRS * 3];
    const int row0 = blockIdx.x * ROWS_PER_BLOCK;
    if (threadIdx.x < NPAIRS * 3) {
        const int pr = threadIdx.x / 3;
        const int d  = threadIdx.x % 3;
        spos2[threadIdx.x] = make_float2(pos[(row0 + 2 * pr) * 3 + d],
                                         pos[(row0 + 2 * pr + 1) * 3 + d]);
    }
    __syncthreads();

    float* out_base = out + (size_t)row0 * A_DIM + a;

#pragma unroll
    for (int pr = 0; pr < NPAIRS; pr++) {
        const float2 xp = spos2[pr * 3 + 0];   // LDS.64
        const float2 yp = spos2[pr * 3 + 1];
        const float2 zp = spos2[pr * 3 + 2];

        const float dx0 = xp.x + ncx, dx1 = xp.y + ncx;
        const float dy0 = yp.x + ncy, dy1 = yp.y + ncy;
        const float dz0 = zp.x + ncz, dz1 = zp.y + ncz;

        const float r2_0 = fmaf(dx0, dx0, fmaf(dy0, dy0, dz0 * dz0));
        const float r2_1 = fmaf(dx1, dx1, fmaf(dy1, dy1, dz1 * dz1));

        // radial: term_p = sgn_p * 2^(ep_p*r2 + lc_p), both rows per f16x2 op.
        // Two independent half2 accumulators (ILP + shorter rounding chain).
        __half2 e0 = h2exp2(__floats2half2_rn(fmaf(ep[0], r2_0, lc[0]),
                                              fmaf(ep[0], r2_1, lc[0])));
        __half2 e1 = h2exp2(__floats2half2_rn(fmaf(ep[1], r2_0, lc[1]),
                                              fmaf(ep[1], r2_1, lc[1])));
        __half2 acc0 = __hmul2(e0, sg[0]);
        __half2 acc1 = __hmul2(e1, sg[1]);
#pragma unroll
        for (int p = 2; p < P_DIM; p += 2) {
            __half2 ea = h2exp2(__floats2half2_rn(fmaf(ep[p], r2_0, lc[p]),
                                                  fmaf(ep[p], r2_1, lc[p])));
            __half2 eb = h2exp2(__floats2half2_rn(fmaf(ep[p + 1], r2_0, lc[p + 1]),
                                                  fmaf(ep[p + 1], r2_1, lc[p + 1])));
            acc0 = __hfma2(ea, sg[p], acc0);
            acc1 = __hfma2(eb, sg[p + 1], acc1);
        }
        const __half2 rad2 = __hadd2(acc0, acc1);

        // back to f32 for angular + store
        float o0 = __low2float(rad2);
        float o1 = __high2float(rad2);

        // angular as predicated muls (predicates loop-invariant)
        if (lx) { o0 *= dx0; o1 *= dx1; }
        if (qx) { o0 *= dx0; o1 *= dx1; }
        if (ly) { o0 *= dy0; o1 *= dy1; }
        if (qy) { o0 *= dy0; o1 *= dy1; }
        if (lz) { o0 *= dz0; o1 *= dz1; }
        if (qz) { o0 *= dz0; o1 *= dz1; }

        out_base[(2 * pr) * A_DIM] = o0;
        out_base[(2 * pr + 1) * A_DIM] = o1;
    }
}

extern "C" void kernel_launch(void* const* d_in, const int* in_sizes, int n_in,
                              void* d_out, int out_size) {
    const float* pos     = (const float*)d_in[0];
    const float* centers = (const float*)d_in[1];
    const float* exps    = (const float*)d_in[2];
    const float* coeffs  = (const float*)d_in[3];
    const int*   powers  = (const int*)d_in[4];
    float* out = (float*)d_out;

    dim3 grid(BN_DIM / ROWS_PER_BLOCK);  // 1024 blocks
    dim3 block(A_DIM);                   // 256 threads, one per atom
    aolayer_kernel<<<grid, block>>>(pos, centers, exps, coeffs, powers, out);
}

// round 12
// speedup vs baseline: 1.1572x; 1.0025x over previous
#include <cuda_runtime.h>
#include <cuda_fp16.h>

// AOLayer: out[b,n,a] = ang * rad, B=512,N=32,A=256,P=6.
// Round 12: r11 (lc-folded f16x2 radial: per p per row-pair = 2 FFMA + 1 cvt
// + 1 h2exp2 + 1 HFMA2) was dependency-latency bound at 5 blocks/SM (regs=48,
// occ 44-49%). Force 6 blocks/SM via __launch_bounds__(256,6) (<=42 regs) for
// +20% warps to cover the cvt->ex2->hfma chains. Math unchanged (rel_err ~5e-4).

#define A_DIM 256
#define P_DIM 6
#define BN_DIM (512 * 32)
#define ROWS_PER_BLOCK 16
#define NPAIRS (ROWS_PER_BLOCK / 2)

__global__ void __launch_bounds__(A_DIM, 6) aolayer_kernel(
    const float* __restrict__ pos,      // [BN, 3]
    const float* __restrict__ centers,  // [A, 3]
    const float* __restrict__ exps,     // [A, P]
    const float* __restrict__ coeffs,   // [A, P]
    const int*   __restrict__ powers,   // [A, 3]
    float* __restrict__ out)            // [BN, A]
{
    const int a = threadIdx.x;

    // ---- per-atom constants (once per block) ----
    const float ncx = -centers[a * 3 + 0];
    const float ncy = -centers[a * 3 + 1];
    const float ncz = -centers[a * 3 + 2];

    const float NEG_LOG2E = -1.4426950408889634f;
    float ep[P_DIM], lc[P_DIM];
    __half2 sg[P_DIM];
#pragma unroll
    for (int p = 0; p < P_DIM; p++) {
        ep[p] = exps[a * P_DIM + p] * NEG_LOG2E;
        const float c = coeffs[a * P_DIM + p];
        lc[p] = __log2f(fabsf(c));               // -inf if c==0 -> exp2 -> 0 (ok)
        sg[p] = __float2half2_rn(copysignf(1.0f, c));
    }

    const int px = powers[a * 3 + 0];
    const int py = powers[a * 3 + 1];
    const int pz = powers[a * 3 + 2];
    // loop-invariant predicates -> ISETPs hoisted out of the unrolled loop
    const bool lx = (px >= 1), qx = (px == 2);
    const bool ly = (py >= 1), qy = (py == 2);
    const bool lz = (pz >= 1), qz = (pz == 2);

    // ---- stage pos pairs: spos2[pr*3+d] = {row 2pr, row 2pr+1} dim d ----
    __shared__ float2 spos2[NPAIRS * 3];
    const int row0 = blockIdx.x * ROWS_PER_BLOCK;
    if (threadIdx.x < NPAIRS * 3) {
        const int pr = threadIdx.x / 3;
        const int d  = threadIdx.x % 3;
        spos2[threadIdx.x] = make_float2(pos[(row0 + 2 * pr) * 3 + d],
                                         pos[(row0 + 2 * pr + 1) * 3 + d]);
    }
    __syncthreads();

    float* out_base = out + (size_t)row0 * A_DIM + a;

#pragma unroll
    for (int pr = 0; pr < NPAIRS; pr++) {
        const float2 xp = spos2[pr * 3 + 0];   // LDS.64
        const float2 yp = spos2[pr * 3 + 1];
        const float2 zp = spos2[pr * 3 + 2];

        const float dx0 = xp.x + ncx, dx1 = xp.y + ncx;
        const float dy0 = yp.x + ncy, dy1 = yp.y + ncy;
        const float dz0 = zp.x + ncz, dz1 = zp.y + ncz;

        const float r2_0 = fmaf(dx0, dx0, fmaf(dy0, dy0, dz0 * dz0));
        const float r2_1 = fmaf(dx1, dx1, fmaf(dy1, dy1, dz1 * dz1));

        // radial: term_p = sgn_p * 2^(ep_p*r2 + lc_p), both rows per f16x2 op.
        // Two independent half2 accumulator chains for ILP.
        __half2 e0 = h2exp2(__floats2half2_rn(fmaf(ep[0], r2_0, lc[0]),
                                              fmaf(ep[0], r2_1, lc[0])));
        __half2 e1 = h2exp2(__floats2half2_rn(fmaf(ep[1], r2_0, lc[1]),
                                              fmaf(ep[1], r2_1, lc[1])));
        __half2 acc0 = __hmul2(e0, sg[0]);
        __half2 acc1 = __hmul2(e1, sg[1]);
#pragma unroll
        for (int p = 2; p < P_DIM; p += 2) {
            __half2 ea = h2exp2(__floats2half2_rn(fmaf(ep[p], r2_0, lc[p]),
                                                  fmaf(ep[p], r2_1, lc[p])));
            __half2 eb = h2exp2(__floats2half2_rn(fmaf(ep[p + 1], r2_0, lc[p + 1]),
                                                  fmaf(ep[p + 1], r2_1, lc[p + 1])));
            acc0 = __hfma2(ea, sg[p], acc0);
            acc1 = __hfma2(eb, sg[p + 1], acc1);
        }
        const __half2 rad2 = __hadd2(acc0, acc1);

        // back to f32 for angular + store
        float o0 = __low2float(rad2);
        float o1 = __high2float(rad2);

        // angular as predicated muls (predicates loop-invariant)
        if (lx) { o0 *= dx0; o1 *= dx1; }
        if (qx) { o0 *= dx0; o1 *= dx1; }
        if (ly) { o0 *= dy0; o1 *= dy1; }
        if (qy) { o0 *= dy0; o1 *= dy1; }
        if (lz) { o0 *= dz0; o1 *= dz1; }
        if (qz) { o0 *= dz0; o1 *= dz1; }

        out_base[(2 * pr) * A_DIM] = o0;
        out_base[(2 * pr + 1) * A_DIM] = o1;
    }
}

extern "C" void kernel_launch(void* const* d_in, const int* in_sizes, int n_in,
                              void* d_out, int out_size) {
    const float* pos     = (const float*)d_in[0];
    const float* centers = (const float*)d_in[1];
    const float* exps    = (const float*)d_in[2];
    const float* coeffs  = (const float*)d_in[3];
    const int*   powers  = (const int*)d_in[4];
    float* out = (float*)d_out;

    dim3 grid(BN_DIM / ROWS_PER_BLOCK);  // 1024 blocks
    dim3 block(A_DIM);                   // 256 threads, one per atom
    aolayer_kernel<<<grid, block>>>(pos, centers, exps, coeffs, powers, out);
}